// round 1
// baseline (speedup 1.0000x reference)
#include <cuda_runtime.h>
#include <cuda_bf16.h>
#include <math.h>

// Problem constants
#define BB 2
#define SS 1024
#define DD 768
#define HH 12
#define HD 64
#define DFF 3072
#define TD 2304           // 3*D
#define MROWS (BB*SS)     // 2048

// ---------------- scratch (__device__ globals; no allocation) ----------------
__device__ float g_xln[MROWS * DD];        // LN output (reused for ln1 and ln2)
__device__ float g_qkv[MROWS * TD];        // QKV projection
__device__ float g_attnout[MROWS * DD];    // attention output (pre O-proj)
__device__ float g_res1[MROWS * DD];       // inp + attn@o_w^T
__device__ float g_h1[MROWS * DFF];        // relu(mlp1)

// ---------------- LayerNorm: one block per row ----------------
__global__ void ln_kernel(const float* __restrict__ x,
                          const float* __restrict__ g,
                          const float* __restrict__ b,
                          float* __restrict__ y)
{
    __shared__ float s1[256], s2[256];
    int row = blockIdx.x;
    const float* xr = x + (size_t)row * DD;
    float* yr = y + (size_t)row * DD;
    int tid = threadIdx.x;

    float v0 = xr[tid], v1 = xr[tid + 256], v2 = xr[tid + 512];
    float sum = v0 + v1 + v2;
    float sq  = v0*v0 + v1*v1 + v2*v2;
    s1[tid] = sum; s2[tid] = sq;
    __syncthreads();
    for (int o = 128; o > 0; o >>= 1) {
        if (tid < o) { s1[tid] += s1[tid+o]; s2[tid] += s2[tid+o]; }
        __syncthreads();
    }
    float mean = s1[0] * (1.0f / DD);
    float var  = s2[0] * (1.0f / DD) - mean * mean;
    float inv  = rsqrtf(var + 1e-5f);
    yr[tid]       = (v0 - mean) * inv * g[tid]       + b[tid];
    yr[tid + 256] = (v1 - mean) * inv * g[tid + 256] + b[tid + 256];
    yr[tid + 512] = (v2 - mean) * inv * g[tid + 512] + b[tid + 512];
}

// ---------------- NT GEMM: C[m][n] = sum_k A[m][k]*B[n][k] (+bias,+resid,relu)
// BM=BN=64, BK=16, 256 threads, each thread 4x4.
__global__ void gemm_nt_kernel(const float* __restrict__ A,
                               const float* __restrict__ B,
                               const float* __restrict__ bias,
                               const float* __restrict__ resid,
                               float* __restrict__ C,
                               int M, int N, int K, int do_relu)
{
    __shared__ float As[16][68];
    __shared__ float Bs[16][68];
    int tid = threadIdx.x;
    int tx = tid & 15, ty = tid >> 4;
    int row0 = blockIdx.y * 64, col0 = blockIdx.x * 64;

    float acc[4][4];
    #pragma unroll
    for (int i = 0; i < 4; i++)
        #pragma unroll
        for (int j = 0; j < 4; j++) acc[i][j] = 0.0f;

    for (int k0 = 0; k0 < K; k0 += 16) {
        #pragma unroll
        for (int i = 0; i < 4; i++) {
            int idx = tid + i * 256;        // 0..1023
            int m = idx >> 4, kk = idx & 15;
            As[kk][m] = A[(size_t)(row0 + m) * K + k0 + kk];
            Bs[kk][m] = B[(size_t)(col0 + m) * K + k0 + kk];
        }
        __syncthreads();
        #pragma unroll
        for (int kk = 0; kk < 16; kk++) {
            float4 a4 = *(const float4*)&As[kk][ty * 4];
            float4 b4 = *(const float4*)&Bs[kk][tx * 4];
            float a[4] = {a4.x, a4.y, a4.z, a4.w};
            float b[4] = {b4.x, b4.y, b4.z, b4.w};
            #pragma unroll
            for (int i = 0; i < 4; i++)
                #pragma unroll
                for (int j = 0; j < 4; j++)
                    acc[i][j] = fmaf(a[i], b[j], acc[i][j]);
        }
        __syncthreads();
    }

    #pragma unroll
    for (int i = 0; i < 4; i++) {
        int r = row0 + ty * 4 + i;
        #pragma unroll
        for (int j = 0; j < 4; j++) {
            int c = col0 + tx * 4 + j;
            float v = acc[i][j];
            if (bias)  v += bias[c];
            if (resid) v += resid[(size_t)r * N + c];
            if (do_relu) v = fmaxf(v, 0.0f);
            C[(size_t)r * N + c] = v;
        }
    }
}

// ---------------- Fused attention ----------------
// Block: (q-tile of 8, head, batch). 256 threads.
// Shared: qs[8*64], r[32], Kt[128*65], sc[8*1024]  => ~68.2 KB dynamic.
#define QT 8
#define KT 128
__global__ void attn_kernel(const float* __restrict__ qkv,
                            const int* __restrict__ relm,
                            const unsigned char* __restrict__ mask,
                            const float* __restrict__ relA,
                            float* __restrict__ out)
{
    extern __shared__ float sm[];
    float* qs = sm;                    // 8*64 = 512
    float* rr = qs + QT * HD;          // 32 (8*3 padded)
    float* Kt = rr + 32;               // 128*65 = 8320
    float* sc = Kt + KT * 65;          // 8*1024 = 8192

    int tid = threadIdx.x;
    int q0 = blockIdx.x * QT;
    int h  = blockIdx.y;
    int b  = blockIdx.z;
    const float* base = qkv + (size_t)b * SS * TD;

    // load Q tile
    for (int i = tid; i < QT * HD; i += 256) {
        int q = i >> 6, d = i & 63;
        qs[i] = base[(size_t)(q0 + q) * TD + h * HD + d];
    }
    __syncthreads();

    // rel projections r[q][c] = q . relA[c]
    if (tid < QT * 3) {
        int q = tid / 3, c = tid % 3;
        float s = 0.0f;
        #pragma unroll
        for (int d = 0; d < HD; d++) s += qs[q * HD + d] * relA[c * HD + d];
        rr[q * 3 + c] = s;
    }

    const float scale = 0.125f;  // 1/sqrt(64)

    // ---- pass 1: scores ----
    for (int k0 = 0; k0 < SS; k0 += KT) {
        __syncthreads();
        for (int i = tid; i < KT * HD; i += 256) {
            int k = i >> 6, d = i & 63;
            Kt[k * 65 + d] = base[(size_t)(k0 + k) * TD + DD + h * HD + d];
        }
        __syncthreads();
        #pragma unroll
        for (int pi = 0; pi < (QT * KT) / 256; pi++) {
            int p = tid + pi * 256;
            int k = p & (KT - 1), q = p >> 7;
            float s = 0.0f;
            #pragma unroll
            for (int d = 0; d < HD; d++) s += qs[q * HD + d] * Kt[k * 65 + d];
            int gk = k0 + k;
            int idx = relm[((size_t)b * SS + (q0 + q)) * SS + gk] + 1;
            s = (s + rr[q * 3 + idx]) * scale;
            if (mask[b * SS + gk]) s = -1e30f;
            sc[q * SS + gk] = s;
        }
    }
    __syncthreads();

    // ---- softmax: one warp per query row ----
    {
        int w = tid >> 5, lane = tid & 31;
        float* row = sc + w * SS;
        float mx = -1e30f;
        for (int k = lane; k < SS; k += 32) mx = fmaxf(mx, row[k]);
        #pragma unroll
        for (int o = 16; o; o >>= 1) mx = fmaxf(mx, __shfl_xor_sync(0xffffffffu, mx, o));
        float sum = 0.0f;
        for (int k = lane; k < SS; k += 32) {
            float e = __expf(row[k] - mx);
            row[k] = e;
            sum += e;
        }
        #pragma unroll
        for (int o = 16; o; o >>= 1) sum += __shfl_xor_sync(0xffffffffu, sum, o);
        float inv = 1.0f / sum;
        for (int k = lane; k < SS; k += 32) row[k] *= inv;
    }

    // ---- pass 2: out = P @ V ----
    int d = tid & 63, qi = tid >> 6;   // qi in 0..3; handles rows qi and qi+4
    float acc0 = 0.0f, acc1 = 0.0f;
    float* Vt = Kt;
    for (int k0 = 0; k0 < SS; k0 += KT) {
        __syncthreads();
        for (int i = tid; i < KT * HD; i += 256) {
            int k = i >> 6, dd = i & 63;
            Vt[k * 65 + dd] = base[(size_t)(k0 + k) * TD + 2 * DD + h * HD + dd];
        }
        __syncthreads();
        #pragma unroll 4
        for (int k = 0; k < KT; k++) {
            float v = Vt[k * 65 + d];
            acc0 = fmaf(sc[qi * SS + k0 + k], v, acc0);
            acc1 = fmaf(sc[(qi + 4) * SS + k0 + k], v, acc1);
        }
    }
    out[((size_t)b * SS + q0 + qi) * DD + h * HD + d] = acc0;
    out[((size_t)b * SS + q0 + qi + 4) * DD + h * HD + d] = acc1;
}

// ---------------- launcher ----------------
extern "C" void kernel_launch(void* const* d_in, const int* in_sizes, int n_in,
                              void* d_out, int out_size)
{
    const float*         inp   = (const float*)d_in[0];
    const unsigned char* mask  = (const unsigned char*)d_in[1];
    const int*           relm  = (const int*)d_in[2];
    const float*         qkv_w = (const float*)d_in[3];
    const float*         relA  = (const float*)d_in[4];
    const float*         o_w   = (const float*)d_in[5];
    const float*         w1    = (const float*)d_in[6];
    const float*         b1    = (const float*)d_in[7];
    const float*         w2    = (const float*)d_in[8];
    const float*         b2    = (const float*)d_in[9];
    const float*         ln1g  = (const float*)d_in[10];
    const float*         ln1b  = (const float*)d_in[11];
    const float*         ln2g  = (const float*)d_in[12];
    const float*         ln2b  = (const float*)d_in[13];
    float* out = (float*)d_out;

    float *xln, *qkv, *attnout, *res1, *h1;
    cudaGetSymbolAddress((void**)&xln,     g_xln);
    cudaGetSymbolAddress((void**)&qkv,     g_qkv);
    cudaGetSymbolAddress((void**)&attnout, g_attnout);
    cudaGetSymbolAddress((void**)&res1,    g_res1);
    cudaGetSymbolAddress((void**)&h1,      g_h1);

    // allow >48KB dynamic shared for attention kernel
    int attn_smem = (QT * HD + 32 + KT * 65 + QT * SS) * (int)sizeof(float);
    cudaFuncSetAttribute(attn_kernel, cudaFuncAttributeMaxDynamicSharedMemorySize, attn_smem);

    // 1) LN1
    ln_kernel<<<MROWS, 256>>>(inp, ln1g, ln1b, xln);

    // 2) QKV = xln @ qkv_w^T     (2048 x 2304 x 768)
    gemm_nt_kernel<<<dim3(TD / 64, MROWS / 64), 256>>>(
        xln, qkv_w, nullptr, nullptr, qkv, MROWS, TD, DD, 0);

    // 3) attention
    attn_kernel<<<dim3(SS / QT, HH, BB), 256, attn_smem>>>(qkv, relm, mask, relA, attnout);

    // 4) res1 = inp + attnout @ o_w^T   (2048 x 768 x 768)
    gemm_nt_kernel<<<dim3(DD / 64, MROWS / 64), 256>>>(
        attnout, o_w, nullptr, inp, res1, MROWS, DD, DD, 0);

    // 5) LN2
    ln_kernel<<<MROWS, 256>>>(res1, ln2g, ln2b, xln);

    // 6) h1 = relu(xln @ w1^T + b1)     (2048 x 3072 x 768)
    gemm_nt_kernel<<<dim3(DFF / 64, MROWS / 64), 256>>>(
        xln, w1, b1, nullptr, h1, MROWS, DFF, DD, 1);

    // 7) out = res1 + h1 @ w2^T + b2    (2048 x 768 x 3072)
    gemm_nt_kernel<<<dim3(DD / 64, MROWS / 64), 256>>>(
        h1, w2, b2, res1, out, MROWS, DD, DFF, 0);
}

// round 6
// speedup vs baseline: 2.1979x; 2.1979x over previous
#include <cuda_runtime.h>
#include <cuda_bf16.h>
#include <math.h>
#include <cstdint>

// Problem constants
#define BB 2
#define SS 1024
#define DD 768
#define HH 12
#define HD 64
#define DFF 3072
#define TD 2304           // 3*D
#define MROWS (BB*SS)     // 2048

// ---------------- scratch (__device__ globals; no allocation) ----------------
__device__ float g_xln[MROWS * DD];
__device__ float g_qkv[MROWS * TD];
__device__ float g_attnout[MROWS * DD];
__device__ float g_res1[MROWS * DD];
__device__ float g_h1[MROWS * DFF];

// ================= helpers =================
__device__ __forceinline__ uint32_t smem_to_u32(const void* p) {
    uint32_t a;
    asm("{ .reg .u64 t; cvta.to.shared.u64 t, %1; cvt.u32.u64 %0, t; }" : "=r"(a) : "l"(p));
    return a;
}
__device__ __forceinline__ void cp16(uint32_t saddr, const void* gaddr) {
    asm volatile("cp.async.cg.shared.global [%0], [%1], 16;" :: "r"(saddr), "l"(gaddr) : "memory");
}
#define CP_COMMIT() asm volatile("cp.async.commit_group;" ::: "memory")
#define CP_WAIT(n)  asm volatile("cp.async.wait_group %0;" :: "n"(n) : "memory")

__device__ __forceinline__ uint32_t tf32c(float v) {
    uint32_t r; asm("cvt.rna.tf32.f32 %0, %1;" : "=r"(r) : "f"(v)); return r;
}
// D = A(16x8) * B(8x8) + D, tf32, row.col
__device__ __forceinline__ void mma8(float* c, const uint32_t* a, const uint32_t* b) {
    asm volatile("mma.sync.aligned.m16n8k8.row.col.f32.tf32.tf32.f32 "
        "{%0,%1,%2,%3}, {%4,%5,%6,%7}, {%8,%9}, {%0,%1,%2,%3};"
        : "+f"(c[0]), "+f"(c[1]), "+f"(c[2]), "+f"(c[3])
        : "r"(a[0]), "r"(a[1]), "r"(a[2]), "r"(a[3]), "r"(b[0]), "r"(b[1]));
}

// ================= tf32 mma GEMM: C[m][n] = sum_k A[m][k]*B[n][k] ================
// BM=BN=128, BK=32. 256 threads = 8 warps (2x4), warp tile 64x32.
#define ASTR 36                       // smem row stride (floats) for A/B tiles
#define STAGE_FLOATS (128 * ASTR * 2) // A + B per stage = 9216
#define GEMM_SMEM (2 * STAGE_FLOATS * 4)  // 73728 bytes

__global__ void __launch_bounds__(256) gemm_mma_kernel(
    const float* __restrict__ A, const float* __restrict__ B,
    const float* __restrict__ bias, const float* __restrict__ resid,
    float* __restrict__ C, int N, int K, int do_relu)
{
    extern __shared__ float sm[];
    uint32_t sb32 = smem_to_u32(sm);
    int tid = threadIdx.x;
    int warp = tid >> 5, lane = tid & 31;
    int g = lane >> 2, t = lane & 3;
    int wm = warp >> 2, wn = warp & 3;             // 2 x 4 warps
    int row0 = blockIdx.y * 128, col0 = blockIdx.x * 128;
    int ktiles = K >> 5;

    const float* gA = A + (size_t)row0 * K;
    const float* gB = B + (size_t)col0 * K;

    float acc[4][4][4];
    #pragma unroll
    for (int i = 0; i < 4; i++)
        #pragma unroll
        for (int j = 0; j < 4; j++)
            #pragma unroll
            for (int e = 0; e < 4; e++) acc[i][j][e] = 0.0f;

    auto load_tile = [&](int kt, int buf) {
        uint32_t s0 = sb32 + buf * STAGE_FLOATS * 4;
        const float* a = gA + kt * 32;
        const float* b = gB + kt * 32;
        #pragma unroll
        for (int j = 0; j < 4; j++) {
            int e = tid + j * 256;           // 0..1023
            int r = e >> 3, c = e & 7;       // 128 rows x 8 chunks of 16B
            uint32_t so = (uint32_t)(r * ASTR + c * 4) * 4;
            cp16(s0 + so, a + (size_t)r * K + c * 4);
            cp16(s0 + 128 * ASTR * 4 + so, b + (size_t)r * K + c * 4);
        }
        CP_COMMIT();
    };

    load_tile(0, 0);

    for (int kt = 0; kt < ktiles; kt++) {
        if (kt + 1 < ktiles) { load_tile(kt + 1, (kt + 1) & 1); CP_WAIT(1); }
        else                 { CP_WAIT(0); }
        __syncthreads();

        const float* As = sm + (kt & 1) * STAGE_FLOATS + wm * 64 * ASTR;
        const float* Bs = sm + (kt & 1) * STAGE_FLOATS + 128 * ASTR + wn * 32 * ASTR;

        #pragma unroll
        for (int ks = 0; ks < 4; ks++) {
            uint32_t af[4][4], bf[4][2];
            #pragma unroll
            for (int mt = 0; mt < 4; mt++) {
                const float* ap = As + (mt * 16 + g) * ASTR + ks * 8 + t;
                af[mt][0] = tf32c(ap[0]);
                af[mt][1] = tf32c(ap[8 * ASTR]);
                af[mt][2] = tf32c(ap[4]);
                af[mt][3] = tf32c(ap[8 * ASTR + 4]);
            }
            #pragma unroll
            for (int nt = 0; nt < 4; nt++) {
                const float* bp = Bs + (nt * 8 + g) * ASTR + ks * 8 + t;
                bf[nt][0] = tf32c(bp[0]);
                bf[nt][1] = tf32c(bp[4]);
            }
            #pragma unroll
            for (int mt = 0; mt < 4; mt++)
                #pragma unroll
                for (int nt = 0; nt < 4; nt++)
                    mma8(acc[mt][nt], af[mt], bf[nt]);
        }
        __syncthreads();
    }

    // epilogue: stage through smem (stride 132), then coalesced fused store
    float* eb = sm;
    #pragma unroll
    for (int mt = 0; mt < 4; mt++) {
        int r0 = wm * 64 + mt * 16 + g;
        #pragma unroll
        for (int nt = 0; nt < 4; nt++) {
            int c0 = wn * 32 + nt * 8 + 2 * t;
            eb[r0 * 132 + c0]           = acc[mt][nt][0];
            eb[r0 * 132 + c0 + 1]       = acc[mt][nt][1];
            eb[(r0 + 8) * 132 + c0]     = acc[mt][nt][2];
            eb[(r0 + 8) * 132 + c0 + 1] = acc[mt][nt][3];
        }
    }
    __syncthreads();

    int c = tid & 127;
    int rs = tid >> 7;
    float bv = bias ? bias[col0 + c] : 0.0f;
    for (int r = rs; r < 128; r += 2) {
        float v = eb[r * 132 + c] + bv;
        size_t off = (size_t)(row0 + r) * N + col0 + c;
        if (resid) v += resid[off];
        if (do_relu) v = fmaxf(v, 0.0f);
        C[off] = v;
    }
}

// ---------------- LayerNorm: one block per row ----------------
__global__ void ln_kernel(const float* __restrict__ x,
                          const float* __restrict__ g,
                          const float* __restrict__ b,
                          float* __restrict__ y)
{
    __shared__ float s1[256], s2[256];
    int row = blockIdx.x;
    const float* xr = x + (size_t)row * DD;
    float* yr = y + (size_t)row * DD;
    int tid = threadIdx.x;

    float v0 = xr[tid], v1 = xr[tid + 256], v2 = xr[tid + 512];
    float sum = v0 + v1 + v2;
    float sq  = v0*v0 + v1*v1 + v2*v2;
    s1[tid] = sum; s2[tid] = sq;
    __syncthreads();
    for (int o = 128; o > 0; o >>= 1) {
        if (tid < o) { s1[tid] += s1[tid+o]; s2[tid] += s2[tid+o]; }
        __syncthreads();
    }
    float mean = s1[0] * (1.0f / DD);
    float var  = s2[0] * (1.0f / DD) - mean * mean;
    float inv  = rsqrtf(var + 1e-5f);
    yr[tid]       = (v0 - mean) * inv * g[tid]       + b[tid];
    yr[tid + 256] = (v1 - mean) * inv * g[tid + 256] + b[tid + 256];
    yr[tid + 512] = (v2 - mean) * inv * g[tid + 512] + b[tid + 512];
}

// ================= mma attention =================
// Block: 16 queries x 1 head x 1 batch. 128 threads (4 warps).
// Pass1: S = Q K^T (+rel, mask, scale) -> sc smem. Softmax. Pass2: O = P V.
#define KSTR 76     // K/V smem row stride (floats) -> conflict-free frag loads
#define SCSTR 1036  // score row stride (floats)
#define QS_OFF 0
#define RR_OFF (16 * KSTR)                  // 1216
#define KS_OFF (RR_OFF + 64)                // 1280
#define SC_OFF (KS_OFF + 2 * 64 * KSTR)     // 11008
#define ATTN_SMEM ((SC_OFF + 16 * SCSTR) * 4)  // 110336 bytes

__global__ void __launch_bounds__(128) attn_mma_kernel(
    const float* __restrict__ qkv,
    const int* __restrict__ relm,
    const unsigned char* __restrict__ mask,
    const float* __restrict__ relA,
    float* __restrict__ out)
{
    extern __shared__ float sm[];
    uint32_t sb32 = smem_to_u32(sm);
    float* Qs = sm + QS_OFF;
    float* rr = sm + RR_OFF;
    float* sc = sm + SC_OFF;

    int tid = threadIdx.x;
    int warp = tid >> 5, lane = tid & 31;
    int g = lane >> 2, t = lane & 3;
    int q0 = blockIdx.x * 16;
    int h  = blockIdx.y;
    int b  = blockIdx.z;
    const float* base = qkv + (size_t)b * SS * TD;
    const int* relrow = relm + ((size_t)b * SS + q0) * SS;
    const unsigned char* maskp = mask + b * SS;

    // load Q tile [16][64]
    for (int i = tid; i < 16 * HD; i += 128) {
        int q = i >> 6, d = i & 63;
        Qs[q * KSTR + d] = base[(size_t)(q0 + q) * TD + h * HD + d];
    }
    __syncthreads();

    // rel projections
    if (tid < 48) {
        int q = tid / 3, c = tid % 3;
        float s = 0.0f;
        #pragma unroll
        for (int d = 0; d < HD; d++) s += Qs[q * KSTR + d] * relA[c * HD + d];
        rr[q * 3 + c] = s;
    }
    __syncthreads();

    // Q fragments in registers (persist whole kernel)
    uint32_t qf[8][4];
    #pragma unroll
    for (int ks = 0; ks < 8; ks++) {
        const float* qp = Qs + g * KSTR + ks * 8 + t;
        qf[ks][0] = tf32c(qp[0]);
        qf[ks][1] = tf32c(qp[8 * KSTR]);
        qf[ks][2] = tf32c(qp[4]);
        qf[ks][3] = tf32c(qp[8 * KSTR + 4]);
    }

    // K/V tile loader: 64 keys x 64 floats (16 KB) into Ks buffer
    // FIXED (R5 bug): full tile = 64 rows x 16 chunks of 16B = 1024 cp16 ops.
    auto load_kv = [&](int kt, int buf, int which) {   // which: 1=K, 2=V
        uint32_t s0 = sb32 + (KS_OFF + buf * 64 * KSTR) * 4;
        const float* src = base + (size_t)kt * 64 * TD + which * DD + h * HD;
        #pragma unroll
        for (int j = 0; j < 8; j++) {
            int e = tid + j * 128;        // 0..1023
            int r = e >> 4, c = e & 15;   // 64 rows x 16 chunks of 16B
            cp16(s0 + (uint32_t)(r * KSTR + c * 4) * 4, src + (size_t)r * TD + c * 4);
        }
        CP_COMMIT();
    };

    // ---- pass 1: scores ----
    load_kv(0, 0, 1);
    for (int kt = 0; kt < 16; kt++) {
        if (kt + 1 < 16) { load_kv(kt + 1, (kt + 1) & 1, 1); CP_WAIT(1); }
        else             { CP_WAIT(0); }
        __syncthreads();

        const float* Kb = sm + KS_OFF + (kt & 1) * 64 * KSTR;
        float accs[2][4] = {{0,0,0,0},{0,0,0,0}};
        #pragma unroll
        for (int ks = 0; ks < 8; ks++) {
            uint32_t bf[2][2];
            #pragma unroll
            for (int nt = 0; nt < 2; nt++) {
                const float* kp = Kb + (warp * 16 + nt * 8 + g) * KSTR + ks * 8 + t;
                bf[nt][0] = tf32c(kp[0]);
                bf[nt][1] = tf32c(kp[4]);
            }
            mma8(accs[0], qf[ks], bf[0]);
            mma8(accs[1], qf[ks], bf[1]);
        }
        // epilogue: rel + scale + mask -> sc
        #pragma unroll
        for (int nt = 0; nt < 2; nt++) {
            #pragma unroll
            for (int e = 0; e < 4; e++) {
                int q  = g + ((e >> 1) ? 8 : 0);
                int gk = kt * 64 + warp * 16 + nt * 8 + 2 * t + (e & 1);
                float s = accs[nt][e];
                int idx = relrow[(size_t)q * SS + gk] + 1;
                s = (s + rr[q * 3 + idx]) * 0.125f;
                if (maskp[gk]) s = -1e30f;
                sc[q * SCSTR + gk] = s;
            }
        }
        __syncthreads();
    }

    // ---- softmax: warp handles rows warp, warp+4, warp+8, warp+12 ----
    #pragma unroll
    for (int ri = 0; ri < 4; ri++) {
        float* row = sc + (warp + ri * 4) * SCSTR;
        float mx = -1e30f;
        for (int k = lane; k < SS; k += 32) mx = fmaxf(mx, row[k]);
        #pragma unroll
        for (int o = 16; o; o >>= 1) mx = fmaxf(mx, __shfl_xor_sync(0xffffffffu, mx, o));
        float sum = 0.0f;
        for (int k = lane; k < SS; k += 32) {
            float e = __expf(row[k] - mx);
            row[k] = e;
            sum += e;
        }
        #pragma unroll
        for (int o = 16; o; o >>= 1) sum += __shfl_xor_sync(0xffffffffu, sum, o);
        float inv = 1.0f / sum;
        for (int k = lane; k < SS; k += 32) row[k] *= inv;
    }
    __syncthreads();

    // ---- pass 2: O = P @ V (warp owns 16 d-columns) ----
    float acco[2][4] = {{0,0,0,0},{0,0,0,0}};
    load_kv(0, 0, 2);
    for (int kt = 0; kt < 16; kt++) {
        if (kt + 1 < 16) { load_kv(kt + 1, (kt + 1) & 1, 2); CP_WAIT(1); }
        else             { CP_WAIT(0); }
        __syncthreads();

        const float* Vb = sm + KS_OFF + (kt & 1) * 64 * KSTR;
        #pragma unroll
        for (int ks = 0; ks < 8; ks++) {
            int k0 = kt * 64 + ks * 8;
            uint32_t af[4];
            const float* pp = sc + g * SCSTR + k0 + t;
            af[0] = tf32c(pp[0]);
            af[1] = tf32c(pp[8 * SCSTR]);
            af[2] = tf32c(pp[4]);
            af[3] = tf32c(pp[8 * SCSTR + 4]);
            uint32_t bf[2][2];
            #pragma unroll
            for (int nt = 0; nt < 2; nt++) {
                const float* vp = Vb + (ks * 8 + t) * KSTR + warp * 16 + nt * 8 + g;
                bf[nt][0] = tf32c(vp[0]);
                bf[nt][1] = tf32c(vp[4 * KSTR]);
            }
            mma8(acco[0], af, bf[0]);
            mma8(acco[1], af, bf[1]);
        }
        __syncthreads();
    }

    #pragma unroll
    for (int nt = 0; nt < 2; nt++) {
        #pragma unroll
        for (int e = 0; e < 4; e++) {
            int q = g + ((e >> 1) ? 8 : 0);
            int d = warp * 16 + nt * 8 + 2 * t + (e & 1);
            out[((size_t)b * SS + q0 + q) * DD + h * HD + d] = acco[nt][e];
        }
    }
}

// ---------------- launcher ----------------
extern "C" void kernel_launch(void* const* d_in, const int* in_sizes, int n_in,
                              void* d_out, int out_size)
{
    const float*         inp   = (const float*)d_in[0];
    const unsigned char* mask  = (const unsigned char*)d_in[1];
    const int*           relm  = (const int*)d_in[2];
    const float*         qkv_w = (const float*)d_in[3];
    const float*         relA  = (const float*)d_in[4];
    const float*         o_w   = (const float*)d_in[5];
    const float*         w1    = (const float*)d_in[6];
    const float*         b1    = (const float*)d_in[7];
    const float*         w2    = (const float*)d_in[8];
    const float*         b2    = (const float*)d_in[9];
    const float*         ln1g  = (const float*)d_in[10];
    const float*         ln1b  = (const float*)d_in[11];
    const float*         ln2g  = (const float*)d_in[12];
    const float*         ln2b  = (const float*)d_in[13];
    float* out = (float*)d_out;

    float *xln, *qkv, *attnout, *res1, *h1;
    cudaGetSymbolAddress((void**)&xln,     g_xln);
    cudaGetSymbolAddress((void**)&qkv,     g_qkv);
    cudaGetSymbolAddress((void**)&attnout, g_attnout);
    cudaGetSymbolAddress((void**)&res1,    g_res1);
    cudaGetSymbolAddress((void**)&h1,      g_h1);

    cudaFuncSetAttribute(gemm_mma_kernel, cudaFuncAttributeMaxDynamicSharedMemorySize, GEMM_SMEM);
    cudaFuncSetAttribute(attn_mma_kernel, cudaFuncAttributeMaxDynamicSharedMemorySize, ATTN_SMEM);

    // 1) LN1
    ln_kernel<<<MROWS, 256>>>(inp, ln1g, ln1b, xln);

    // 2) QKV = xln @ qkv_w^T     (2048 x 2304 x 768)
    gemm_mma_kernel<<<dim3(TD / 128, MROWS / 128), 256, GEMM_SMEM>>>(
        xln, qkv_w, nullptr, nullptr, qkv, TD, DD, 0);

    // 3) attention
    attn_mma_kernel<<<dim3(SS / 16, HH, BB), 128, ATTN_SMEM>>>(qkv, relm, mask, relA, attnout);

    // 4) res1 = inp + attnout @ o_w^T   (2048 x 768 x 768)
    gemm_mma_kernel<<<dim3(DD / 128, MROWS / 128), 256, GEMM_SMEM>>>(
        attnout, o_w, nullptr, inp, res1, DD, DD, 0);

    // 5) LN2
    ln_kernel<<<MROWS, 256>>>(res1, ln2g, ln2b, xln);

    // 6) h1 = relu(xln @ w1^T + b1)     (2048 x 3072 x 768)
    gemm_mma_kernel<<<dim3(DFF / 128, MROWS / 128), 256, GEMM_SMEM>>>(
        xln, w1, b1, nullptr, h1, DFF, DD, 1);

    // 7) out = res1 + h1 @ w2^T + b2    (2048 x 768 x 3072)
    gemm_mma_kernel<<<dim3(DD / 128, MROWS / 128), 256, GEMM_SMEM>>>(
        h1, w2, b2, res1, out, DD, DFF, 0);
}

// round 7
// speedup vs baseline: 3.8121x; 1.7344x over previous
#include <cuda_runtime.h>
#include <cuda_bf16.h>
#include <math.h>
#include <cstdint>

// Problem constants
#define BB 2
#define SS 1024
#define DD 768
#define HH 12
#define HD 64
#define DFF 3072
#define TD 2304           // 3*D
#define MROWS (BB*SS)     // 2048

// ---------------- scratch (__device__ globals; no allocation) ----------------
__device__ float g_xln[MROWS * DD];
__device__ float g_qkv[MROWS * TD];
__device__ float g_attnout[MROWS * DD];
__device__ float g_res1[MROWS * DD];
__device__ float g_h1[MROWS * DFF];
__device__ unsigned char g_relpack[BB * SS * SS];   // rel_matrix + 1 as u8

// ================= helpers =================
__device__ __forceinline__ uint32_t smem_to_u32(const void* p) {
    uint32_t a;
    asm("{ .reg .u64 t; cvta.to.shared.u64 t, %1; cvt.u32.u64 %0, t; }" : "=r"(a) : "l"(p));
    return a;
}
__device__ __forceinline__ void cp16(uint32_t saddr, const void* gaddr) {
    asm volatile("cp.async.cg.shared.global [%0], [%1], 16;" :: "r"(saddr), "l"(gaddr) : "memory");
}
#define CP_COMMIT() asm volatile("cp.async.commit_group;" ::: "memory")
#define CP_WAIT(n)  asm volatile("cp.async.wait_group %0;" :: "n"(n) : "memory")

__device__ __forceinline__ uint32_t tf32c(float v) {
    uint32_t r; asm("cvt.rna.tf32.f32 %0, %1;" : "=r"(r) : "f"(v)); return r;
}
// D = A(16x8) * B(8x8) + D, tf32, row.col
__device__ __forceinline__ void mma8(float* c, const uint32_t* a, const uint32_t* b) {
    asm volatile("mma.sync.aligned.m16n8k8.row.col.f32.tf32.tf32.f32 "
        "{%0,%1,%2,%3}, {%4,%5,%6,%7}, {%8,%9}, {%0,%1,%2,%3};"
        : "+f"(c[0]), "+f"(c[1]), "+f"(c[2]), "+f"(c[3])
        : "r"(a[0]), "r"(a[1]), "r"(a[2]), "r"(a[3]), "r"(b[0]), "r"(b[1]));
}

// ================= tf32 mma GEMM (unchanged from R6) ================
#define ASTR 36
#define STAGE_FLOATS (128 * ASTR * 2)
#define GEMM_SMEM (2 * STAGE_FLOATS * 4)

__global__ void __launch_bounds__(256) gemm_mma_kernel(
    const float* __restrict__ A, const float* __restrict__ B,
    const float* __restrict__ bias, const float* __restrict__ resid,
    float* __restrict__ C, int N, int K, int do_relu)
{
    extern __shared__ float sm[];
    uint32_t sb32 = smem_to_u32(sm);
    int tid = threadIdx.x;
    int warp = tid >> 5, lane = tid & 31;
    int g = lane >> 2, t = lane & 3;
    int wm = warp >> 2, wn = warp & 3;
    int row0 = blockIdx.y * 128, col0 = blockIdx.x * 128;
    int ktiles = K >> 5;

    const float* gA = A + (size_t)row0 * K;
    const float* gB = B + (size_t)col0 * K;

    float acc[4][4][4];
    #pragma unroll
    for (int i = 0; i < 4; i++)
        #pragma unroll
        for (int j = 0; j < 4; j++)
            #pragma unroll
            for (int e = 0; e < 4; e++) acc[i][j][e] = 0.0f;

    auto load_tile = [&](int kt, int buf) {
        uint32_t s0 = sb32 + buf * STAGE_FLOATS * 4;
        const float* a = gA + kt * 32;
        const float* b = gB + kt * 32;
        #pragma unroll
        for (int j = 0; j < 4; j++) {
            int e = tid + j * 256;
            int r = e >> 3, c = e & 7;
            uint32_t so = (uint32_t)(r * ASTR + c * 4) * 4;
            cp16(s0 + so, a + (size_t)r * K + c * 4);
            cp16(s0 + 128 * ASTR * 4 + so, b + (size_t)r * K + c * 4);
        }
        CP_COMMIT();
    };

    load_tile(0, 0);

    for (int kt = 0; kt < ktiles; kt++) {
        if (kt + 1 < ktiles) { load_tile(kt + 1, (kt + 1) & 1); CP_WAIT(1); }
        else                 { CP_WAIT(0); }
        __syncthreads();

        const float* As = sm + (kt & 1) * STAGE_FLOATS + wm * 64 * ASTR;
        const float* Bs = sm + (kt & 1) * STAGE_FLOATS + 128 * ASTR + wn * 32 * ASTR;

        #pragma unroll
        for (int ks = 0; ks < 4; ks++) {
            uint32_t af[4][4], bf[4][2];
            #pragma unroll
            for (int mt = 0; mt < 4; mt++) {
                const float* ap = As + (mt * 16 + g) * ASTR + ks * 8 + t;
                af[mt][0] = tf32c(ap[0]);
                af[mt][1] = tf32c(ap[8 * ASTR]);
                af[mt][2] = tf32c(ap[4]);
                af[mt][3] = tf32c(ap[8 * ASTR + 4]);
            }
            #pragma unroll
            for (int nt = 0; nt < 4; nt++) {
                const float* bp = Bs + (nt * 8 + g) * ASTR + ks * 8 + t;
                bf[nt][0] = tf32c(bp[0]);
                bf[nt][1] = tf32c(bp[4]);
            }
            #pragma unroll
            for (int mt = 0; mt < 4; mt++)
                #pragma unroll
                for (int nt = 0; nt < 4; nt++)
                    mma8(acc[mt][nt], af[mt], bf[nt]);
        }
        __syncthreads();
    }

    float* eb = sm;
    #pragma unroll
    for (int mt = 0; mt < 4; mt++) {
        int r0 = wm * 64 + mt * 16 + g;
        #pragma unroll
        for (int nt = 0; nt < 4; nt++) {
            int c0 = wn * 32 + nt * 8 + 2 * t;
            eb[r0 * 132 + c0]           = acc[mt][nt][0];
            eb[r0 * 132 + c0 + 1]       = acc[mt][nt][1];
            eb[(r0 + 8) * 132 + c0]     = acc[mt][nt][2];
            eb[(r0 + 8) * 132 + c0 + 1] = acc[mt][nt][3];
        }
    }
    __syncthreads();

    int c = tid & 127;
    int rs = tid >> 7;
    float bv = bias ? bias[col0 + c] : 0.0f;
    for (int r = rs; r < 128; r += 2) {
        float v = eb[r * 132 + c] + bv;
        size_t off = (size_t)(row0 + r) * N + col0 + c;
        if (resid) v += resid[off];
        if (do_relu) v = fmaxf(v, 0.0f);
        C[off] = v;
    }
}

// ---------------- LayerNorm ----------------
__global__ void ln_kernel(const float* __restrict__ x,
                          const float* __restrict__ g,
                          const float* __restrict__ b,
                          float* __restrict__ y)
{
    __shared__ float s1[256], s2[256];
    int row = blockIdx.x;
    const float* xr = x + (size_t)row * DD;
    float* yr = y + (size_t)row * DD;
    int tid = threadIdx.x;

    float v0 = xr[tid], v1 = xr[tid + 256], v2 = xr[tid + 512];
    float sum = v0 + v1 + v2;
    float sq  = v0*v0 + v1*v1 + v2*v2;
    s1[tid] = sum; s2[tid] = sq;
    __syncthreads();
    for (int o = 128; o > 0; o >>= 1) {
        if (tid < o) { s1[tid] += s1[tid+o]; s2[tid] += s2[tid+o]; }
        __syncthreads();
    }
    float mean = s1[0] * (1.0f / DD);
    float var  = s2[0] * (1.0f / DD) - mean * mean;
    float inv  = rsqrtf(var + 1e-5f);
    yr[tid]       = (v0 - mean) * inv * g[tid]       + b[tid];
    yr[tid + 256] = (v1 - mean) * inv * g[tid + 256] + b[tid + 256];
    yr[tid + 512] = (v2 - mean) * inv * g[tid + 512] + b[tid + 512];
}

// ---------------- rel_matrix pack: idx = relm + 1 as u8 ----------------
__global__ void pack_kernel(const int* __restrict__ relm, unsigned char* __restrict__ out, int n)
{
    int i = blockIdx.x * 256 + threadIdx.x;
    if (i < n) out[i] = (unsigned char)(relm[i] + 1);
}

// ================= flash attention (tf32 mma, online softmax) =================
// CTA: 64 queries x head x batch. 256 threads = 8 warps: warp grid 4(q) x 2(k/d).
// K-tiles of 64 keys, K+V double-buffered cp.async, P via smem, O in regs.
#define AKSTR 76
#define PSTR 68
#define FKS_OFF 0                        // K: 2 x 64 x AKSTR = 9728
#define FVS_OFF (2 * 64 * AKSTR)         // V: 9728
#define FPQ_OFF (FVS_OFF + 2 * 64 * AKSTR)   // P / Q staging: 64 x PSTR = 4352
#define FRR_OFF (FPQ_OFF + 64 * PSTR)    // rr: 192
#define FM_OFF  (FRR_OFF + 192)          // m: 64
#define FL_OFF  (FM_OFF + 64)            // l: 64
#define FSC_OFF (FL_OFF + 64)            // scale: 64
#define FPM_OFF (FSC_OFF + 64)           // partial max: 128
#define FPS_OFF (FPM_OFF + 128)          // partial sum: 128
#define FATTN_FLOATS (FPS_OFF + 128)     // 24448
#define FATTN_SMEM (FATTN_FLOATS * 4)    // 97792 bytes

__global__ void __launch_bounds__(256, 2) flash_attn_kernel(
    const float* __restrict__ qkv,
    const unsigned char* __restrict__ relpack,
    const unsigned char* __restrict__ mask,
    const float* __restrict__ relA,
    float* __restrict__ out)
{
    extern __shared__ float sm[];
    uint32_t sb32 = smem_to_u32(sm);
    float* Pq  = sm + FPQ_OFF;
    float* rr  = sm + FRR_OFF;
    float* m_s = sm + FM_OFF;
    float* l_s = sm + FL_OFF;
    float* sc_s= sm + FSC_OFF;
    float* pm  = sm + FPM_OFF;
    float* ps  = sm + FPS_OFF;

    int tid = threadIdx.x;
    int warp = tid >> 5, lane = tid & 31;
    int g = lane >> 2, t = lane & 3;
    int wq = warp & 3, wk = warp >> 2;
    int q0 = blockIdx.x * 64;
    int h  = blockIdx.y;
    int b  = blockIdx.z;
    const float* base = qkv + (size_t)b * SS * TD;
    const unsigned char* relrow = relpack + ((size_t)b * SS + q0) * SS;
    const unsigned char* maskp = mask + b * SS;

    // stage Q [64][64] into Pq; init stats
    for (int i = tid; i < 64 * HD; i += 256) {
        int q = i >> 6, d = i & 63;
        Pq[q * PSTR + d] = base[(size_t)(q0 + q) * TD + h * HD + d];
    }
    if (tid < 64) { m_s[tid] = -1e30f; l_s[tid] = 0.0f; }
    __syncthreads();

    // rel projections rr[q][c]
    if (tid < 192) {
        int q = tid / 3, c = tid % 3;
        float s = 0.0f;
        #pragma unroll
        for (int d = 0; d < HD; d++) s += Pq[q * PSTR + d] * relA[c * HD + d];
        rr[q * 3 + c] = s;
    }

    // Q fragments (16 q rows per warp, duplicated across wk pair)
    uint32_t qf[8][4];
    #pragma unroll
    for (int ks = 0; ks < 8; ks++) {
        const float* qp = Pq + (wq * 16 + g) * PSTR + ks * 8 + t;
        qf[ks][0] = tf32c(qp[0]);
        qf[ks][1] = tf32c(qp[8 * PSTR]);
        qf[ks][2] = tf32c(qp[4]);
        qf[ks][3] = tf32c(qp[8 * PSTR + 4]);
    }
    __syncthreads();   // Pq free for P use; rr done

    // K+V loader: 64 rows x 64 floats each (16 KB each), 8 cp16/thread
    auto load_tile = [&](int kt, int buf) {
        uint32_t sK = sb32 + (FKS_OFF + buf * 64 * AKSTR) * 4;
        uint32_t sV = sb32 + (FVS_OFF + buf * 64 * AKSTR) * 4;
        const float* srcK = base + (size_t)kt * 64 * TD + DD + h * HD;
        const float* srcV = base + (size_t)kt * 64 * TD + 2 * DD + h * HD;
        #pragma unroll
        for (int j = 0; j < 4; j++) {
            int e = tid + j * 256;
            int r = e >> 4, c = e & 15;
            uint32_t so = (uint32_t)(r * AKSTR + c * 4) * 4;
            cp16(sK + so, srcK + (size_t)r * TD + c * 4);
            cp16(sV + so, srcV + (size_t)r * TD + c * 4);
        }
        CP_COMMIT();
    };

    float oacc[4][4];
    #pragma unroll
    for (int nt = 0; nt < 4; nt++)
        #pragma unroll
        for (int e = 0; e < 4; e++) oacc[nt][e] = 0.0f;

    load_tile(0, 0);

    for (int kt = 0; kt < 16; kt++) {
        int buf = kt & 1;
        if (kt + 1 < 16) { load_tile(kt + 1, (kt + 1) & 1); CP_WAIT(1); }
        else             { CP_WAIT(0); }
        __syncthreads();                    // K/V ready; prev tile fully consumed

        // prefetch rel idx + mask bytes (hide L2 latency under mma)
        unsigned idxv[4][4];
        unsigned mv[4][2];
        #pragma unroll
        for (int nt = 0; nt < 4; nt++) {
            #pragma unroll
            for (int e = 0; e < 4; e++) {
                int q  = wq * 16 + g + 8 * (e >> 1);
                int gk = kt * 64 + wk * 32 + nt * 8 + 2 * t + (e & 1);
                idxv[nt][e] = relrow[(size_t)q * SS + gk];
            }
            int gk0 = kt * 64 + wk * 32 + nt * 8 + 2 * t;
            mv[nt][0] = maskp[gk0];
            mv[nt][1] = maskp[gk0 + 1];
        }

        // S = Q K^T (warp: 16q x 32k)
        float sacc[4][4];
        #pragma unroll
        for (int nt = 0; nt < 4; nt++)
            #pragma unroll
            for (int e = 0; e < 4; e++) sacc[nt][e] = 0.0f;
        const float* Kb = sm + FKS_OFF + buf * 64 * AKSTR;
        #pragma unroll
        for (int ks = 0; ks < 8; ks++) {
            uint32_t bf[4][2];
            #pragma unroll
            for (int nt = 0; nt < 4; nt++) {
                const float* kp = Kb + (wk * 32 + nt * 8 + g) * AKSTR + ks * 8 + t;
                bf[nt][0] = tf32c(kp[0]);
                bf[nt][1] = tf32c(kp[4]);
            }
            #pragma unroll
            for (int nt = 0; nt < 4; nt++)
                mma8(sacc[nt], qf[ks], bf[nt]);
        }

        // epilogue: rel + scale + mask; partial row max
        float rowmax[2] = {-1e30f, -1e30f};
        #pragma unroll
        for (int nt = 0; nt < 4; nt++) {
            #pragma unroll
            for (int e = 0; e < 4; e++) {
                int qr = wq * 16 + g + 8 * (e >> 1);
                float s = (sacc[nt][e] + rr[qr * 3 + idxv[nt][e]]) * 0.125f;
                if (mv[nt][e & 1]) s = -1e30f;
                sacc[nt][e] = s;
                rowmax[e >> 1] = fmaxf(rowmax[e >> 1], s);
            }
        }
        #pragma unroll
        for (int o = 1; o <= 2; o <<= 1) {
            rowmax[0] = fmaxf(rowmax[0], __shfl_xor_sync(0xffffffffu, rowmax[0], o));
            rowmax[1] = fmaxf(rowmax[1], __shfl_xor_sync(0xffffffffu, rowmax[1], o));
        }
        if (t == 0) {
            pm[wk * 64 + wq * 16 + g]     = rowmax[0];
            pm[wk * 64 + wq * 16 + 8 + g] = rowmax[1];
        }
        __syncthreads();

        if (tid < 64) {
            float mo = m_s[tid];
            float mn = fmaxf(mo, fmaxf(pm[tid], pm[64 + tid]));
            m_s[tid] = mn;
            sc_s[tid] = __expf(mo - mn);
        }
        __syncthreads();

        // P = exp(s - m); partial row sums; rescale O
        float rowsum[2] = {0.0f, 0.0f};
        float mrow0 = m_s[wq * 16 + g], mrow1 = m_s[wq * 16 + 8 + g];
        #pragma unroll
        for (int nt = 0; nt < 4; nt++) {
            #pragma unroll
            for (int e = 0; e < 4; e++) {
                int qr = wq * 16 + g + 8 * (e >> 1);
                float p = __expf(sacc[nt][e] - ((e >> 1) ? mrow1 : mrow0));
                rowsum[e >> 1] += p;
                Pq[qr * PSTR + wk * 32 + nt * 8 + 2 * t + (e & 1)] = p;
            }
        }
        #pragma unroll
        for (int o = 1; o <= 2; o <<= 1) {
            rowsum[0] += __shfl_xor_sync(0xffffffffu, rowsum[0], o);
            rowsum[1] += __shfl_xor_sync(0xffffffffu, rowsum[1], o);
        }
        if (t == 0) {
            ps[wk * 64 + wq * 16 + g]     = rowsum[0];
            ps[wk * 64 + wq * 16 + 8 + g] = rowsum[1];
        }
        float s0 = sc_s[wq * 16 + g], s1 = sc_s[wq * 16 + 8 + g];
        #pragma unroll
        for (int nt = 0; nt < 4; nt++) {
            oacc[nt][0] *= s0; oacc[nt][1] *= s0;
            oacc[nt][2] *= s1; oacc[nt][3] *= s1;
        }
        __syncthreads();

        if (tid < 64)
            l_s[tid] = l_s[tid] * sc_s[tid] + ps[tid] + ps[64 + tid];

        // O += P @ V (warp: 16q x 32d, d0 = wk*32)
        const float* Vb = sm + FVS_OFF + buf * 64 * AKSTR;
        #pragma unroll
        for (int ks = 0; ks < 8; ks++) {
            uint32_t af[4];
            const float* pp = Pq + (wq * 16 + g) * PSTR + ks * 8 + t;
            af[0] = tf32c(pp[0]);
            af[1] = tf32c(pp[8 * PSTR]);
            af[2] = tf32c(pp[4]);
            af[3] = tf32c(pp[8 * PSTR + 4]);
            uint32_t bf[4][2];
            #pragma unroll
            for (int nt = 0; nt < 4; nt++) {
                const float* vp = Vb + (ks * 8 + t) * AKSTR + wk * 32 + nt * 8 + g;
                bf[nt][0] = tf32c(vp[0]);
                bf[nt][1] = tf32c(vp[4 * AKSTR]);
            }
            #pragma unroll
            for (int nt = 0; nt < 4; nt++)
                mma8(oacc[nt], af, bf[nt]);
        }
    }
    __syncthreads();   // l_s final

    float inv0 = 1.0f / l_s[wq * 16 + g];
    float inv1 = 1.0f / l_s[wq * 16 + 8 + g];
    #pragma unroll
    for (int nt = 0; nt < 4; nt++) {
        #pragma unroll
        for (int e = 0; e < 4; e++) {
            int qr = wq * 16 + g + 8 * (e >> 1);
            int d  = wk * 32 + nt * 8 + 2 * t + (e & 1);
            out[((size_t)b * SS + q0 + qr) * DD + h * HD + d] =
                oacc[nt][e] * ((e >> 1) ? inv1 : inv0);
        }
    }
}

// ---------------- launcher ----------------
extern "C" void kernel_launch(void* const* d_in, const int* in_sizes, int n_in,
                              void* d_out, int out_size)
{
    const float*         inp   = (const float*)d_in[0];
    const unsigned char* mask  = (const unsigned char*)d_in[1];
    const int*           relm  = (const int*)d_in[2];
    const float*         qkv_w = (const float*)d_in[3];
    const float*         relA  = (const float*)d_in[4];
    const float*         o_w   = (const float*)d_in[5];
    const float*         w1    = (const float*)d_in[6];
    const float*         b1    = (const float*)d_in[7];
    const float*         w2    = (const float*)d_in[8];
    const float*         b2    = (const float*)d_in[9];
    const float*         ln1g  = (const float*)d_in[10];
    const float*         ln1b  = (const float*)d_in[11];
    const float*         ln2g  = (const float*)d_in[12];
    const float*         ln2b  = (const float*)d_in[13];
    float* out = (float*)d_out;

    float *xln, *qkv, *attnout, *res1, *h1;
    unsigned char* relpack;
    cudaGetSymbolAddress((void**)&xln,     g_xln);
    cudaGetSymbolAddress((void**)&qkv,     g_qkv);
    cudaGetSymbolAddress((void**)&attnout, g_attnout);
    cudaGetSymbolAddress((void**)&res1,    g_res1);
    cudaGetSymbolAddress((void**)&h1,      g_h1);
    cudaGetSymbolAddress((void**)&relpack, g_relpack);

    cudaFuncSetAttribute(gemm_mma_kernel, cudaFuncAttributeMaxDynamicSharedMemorySize, GEMM_SMEM);
    cudaFuncSetAttribute(flash_attn_kernel, cudaFuncAttributeMaxDynamicSharedMemorySize, FATTN_SMEM);

    // 0) pack rel indices to u8 (independent; overlaps with LN1/QKV)
    pack_kernel<<<(BB * SS * SS + 255) / 256, 256>>>(relm, relpack, BB * SS * SS);

    // 1) LN1
    ln_kernel<<<MROWS, 256>>>(inp, ln1g, ln1b, xln);

    // 2) QKV = xln @ qkv_w^T     (2048 x 2304 x 768)
    gemm_mma_kernel<<<dim3(TD / 128, MROWS / 128), 256, GEMM_SMEM>>>(
        xln, qkv_w, nullptr, nullptr, qkv, TD, DD, 0);

    // 3) flash attention
    flash_attn_kernel<<<dim3(SS / 64, HH, BB), 256, FATTN_SMEM>>>(
        qkv, relpack, mask, relA, attnout);

    // 4) res1 = inp + attnout @ o_w^T   (2048 x 768 x 768)
    gemm_mma_kernel<<<dim3(DD / 128, MROWS / 128), 256, GEMM_SMEM>>>(
        attnout, o_w, nullptr, inp, res1, DD, DD, 0);

    // 5) LN2
    ln_kernel<<<MROWS, 256>>>(res1, ln2g, ln2b, xln);

    // 6) h1 = relu(xln @ w1^T + b1)     (2048 x 3072 x 768)
    gemm_mma_kernel<<<dim3(DFF / 128, MROWS / 128), 256, GEMM_SMEM>>>(
        xln, w1, b1, nullptr, h1, DFF, DD, 1);

    // 7) out = res1 + h1 @ w2^T + b2    (2048 x 768 x 3072)
    gemm_mma_kernel<<<dim3(DD / 128, MROWS / 128), 256, GEMM_SMEM>>>(
        h1, w2, b2, res1, out, DD, DFF, 0);
}

// round 8
// speedup vs baseline: 4.0703x; 1.0677x over previous
#include <cuda_runtime.h>
#include <cuda_bf16.h>
#include <math.h>
#include <cstdint>

// Problem constants
#define BB 2
#define SS 1024
#define DD 768
#define HH 12
#define HD 64
#define DFF 3072
#define TD 2304           // 3*D
#define MROWS (BB*SS)     // 2048

// weight scratch offsets (floats)
#define W_QKV_OFF 0
#define W_O_OFF   (TD * DD)                    // 1769472
#define W_W1_OFF  (W_O_OFF + DD * DD)          // 2359296
#define W_W2_OFF  (W_W1_OFF + DFF * DD)        // 4718592
#define W_TOTAL   (W_W2_OFF + DD * DFF)        // 7077888

// ---------------- scratch (__device__ globals; no allocation) ----------------
__device__ float g_xln[MROWS * DD];
__device__ float g_qkv[MROWS * TD];
__device__ float g_attnout[MROWS * DD];
__device__ float g_res1[MROWS * DD];
__device__ float g_h1[MROWS * DFF];
__device__ float g_wr[W_TOTAL];
__device__ unsigned char g_relpack[BB * SS * SS];

// ================= helpers =================
__device__ __forceinline__ uint32_t smem_to_u32(const void* p) {
    uint32_t a;
    asm("{ .reg .u64 t; cvta.to.shared.u64 t, %1; cvt.u32.u64 %0, t; }" : "=r"(a) : "l"(p));
    return a;
}
__device__ __forceinline__ void cp16(uint32_t saddr, const void* gaddr) {
    asm volatile("cp.async.cg.shared.global [%0], [%1], 16;" :: "r"(saddr), "l"(gaddr) : "memory");
}
#define CP_COMMIT() asm volatile("cp.async.commit_group;" ::: "memory")
#define CP_WAIT(n)  asm volatile("cp.async.wait_group %0;" :: "n"(n) : "memory")

__device__ __forceinline__ uint32_t tf32c(float v) {
    uint32_t r; asm("cvt.rna.tf32.f32 %0, %1;" : "=r"(r) : "f"(v)); return r;
}
__device__ __forceinline__ float tf32r(float v) {   // round fp32 -> tf32-valued fp32
    return __uint_as_float(tf32c(v));
}
// D = A(16x8) * B(8x8) + D, tf32, row.col
__device__ __forceinline__ void mma8(float* c, const uint32_t* a, const uint32_t* b) {
    asm volatile("mma.sync.aligned.m16n8k8.row.col.f32.tf32.tf32.f32 "
        "{%0,%1,%2,%3}, {%4,%5,%6,%7}, {%8,%9}, {%0,%1,%2,%3};"
        : "+f"(c[0]), "+f"(c[1]), "+f"(c[2]), "+f"(c[3])
        : "r"(a[0]), "r"(a[1]), "r"(a[2]), "r"(a[3]), "r"(b[0]), "r"(b[1]));
}
#define F2U(x) __float_as_uint(x)

// ================= tf32 mma GEMM (pre-rounded operands, 3-stage) ================
// BM=BN=128, BK=32. 256 threads = 8 warps (2x4), warp tile 64x32.
#define ASTR 36
#define STAGE_FLOATS (128 * ASTR * 2)            // 9216
#define GEMM_SMEM (3 * STAGE_FLOATS * 4)         // 110592 bytes

__global__ void __launch_bounds__(256) gemm_mma_kernel(
    const float* __restrict__ A, const float* __restrict__ B,
    const float* __restrict__ bias, const float* __restrict__ resid,
    float* __restrict__ C, int N, int K, int do_relu, int round_out)
{
    extern __shared__ float sm[];
    uint32_t sb32 = smem_to_u32(sm);
    int tid = threadIdx.x;
    int warp = tid >> 5, lane = tid & 31;
    int g = lane >> 2, t = lane & 3;
    int wm = warp >> 2, wn = warp & 3;
    int row0 = blockIdx.y * 128, col0 = blockIdx.x * 128;
    int ktiles = K >> 5;

    const float* gA = A + (size_t)row0 * K;
    const float* gB = B + (size_t)col0 * K;

    float acc[4][4][4];
    #pragma unroll
    for (int i = 0; i < 4; i++)
        #pragma unroll
        for (int j = 0; j < 4; j++)
            #pragma unroll
            for (int e = 0; e < 4; e++) acc[i][j][e] = 0.0f;

    auto load_tile = [&](int kt, int buf) {
        uint32_t s0 = sb32 + buf * STAGE_FLOATS * 4;
        const float* a = gA + kt * 32;
        const float* b = gB + kt * 32;
        #pragma unroll
        for (int j = 0; j < 4; j++) {
            int e = tid + j * 256;
            int r = e >> 3, c = e & 7;
            uint32_t so = (uint32_t)(r * ASTR + c * 4) * 4;
            cp16(s0 + so, a + (size_t)r * K + c * 4);
            cp16(s0 + 128 * ASTR * 4 + so, b + (size_t)r * K + c * 4);
        }
        CP_COMMIT();
    };

    load_tile(0, 0);
    load_tile(1, 1);

    for (int kt = 0; kt < ktiles; kt++) {
        int buf = kt % 3;
        if (kt < ktiles - 1) CP_WAIT(1);
        else                 CP_WAIT(0);
        __syncthreads();                    // prior readers of buf (kt+2)%3 done
        if (kt + 2 < ktiles) load_tile(kt + 2, (kt + 2) % 3);

        const float* As = sm + buf * STAGE_FLOATS + wm * 64 * ASTR;
        const float* Bs = sm + buf * STAGE_FLOATS + 128 * ASTR + wn * 32 * ASTR;

        #pragma unroll
        for (int ks = 0; ks < 4; ks++) {
            uint32_t af[4][4], bf[4][2];
            #pragma unroll
            for (int mt = 0; mt < 4; mt++) {
                const float* ap = As + (mt * 16 + g) * ASTR + ks * 8 + t;
                af[mt][0] = F2U(ap[0]);
                af[mt][1] = F2U(ap[8 * ASTR]);
                af[mt][2] = F2U(ap[4]);
                af[mt][3] = F2U(ap[8 * ASTR + 4]);
            }
            #pragma unroll
            for (int nt = 0; nt < 4; nt++) {
                const float* bp = Bs + (nt * 8 + g) * ASTR + ks * 8 + t;
                bf[nt][0] = F2U(bp[0]);
                bf[nt][1] = F2U(bp[4]);
            }
            #pragma unroll
            for (int mt = 0; mt < 4; mt++)
                #pragma unroll
                for (int nt = 0; nt < 4; nt++)
                    mma8(acc[mt][nt], af[mt], bf[nt]);
        }
    }
    __syncthreads();    // all frag reads done before smem reuse

    float* eb = sm;
    #pragma unroll
    for (int mt = 0; mt < 4; mt++) {
        int r0 = wm * 64 + mt * 16 + g;
        #pragma unroll
        for (int nt = 0; nt < 4; nt++) {
            int c0 = wn * 32 + nt * 8 + 2 * t;
            eb[r0 * 132 + c0]           = acc[mt][nt][0];
            eb[r0 * 132 + c0 + 1]       = acc[mt][nt][1];
            eb[(r0 + 8) * 132 + c0]     = acc[mt][nt][2];
            eb[(r0 + 8) * 132 + c0 + 1] = acc[mt][nt][3];
        }
    }
    __syncthreads();

    int c = tid & 127;
    int rs = tid >> 7;
    float bv = bias ? bias[col0 + c] : 0.0f;
    for (int r = rs; r < 128; r += 2) {
        float v = eb[r * 132 + c] + bv;
        size_t off = (size_t)(row0 + r) * N + col0 + c;
        if (resid) v += resid[off];
        if (do_relu) v = fmaxf(v, 0.0f);
        if (round_out) v = tf32r(v);
        C[off] = v;
    }
}

// ---------------- LayerNorm (writes tf32-rounded output) ----------------
__global__ void ln_kernel(const float* __restrict__ x,
                          const float* __restrict__ g,
                          const float* __restrict__ b,
                          float* __restrict__ y)
{
    __shared__ float s1[256], s2[256];
    int row = blockIdx.x;
    const float* xr = x + (size_t)row * DD;
    float* yr = y + (size_t)row * DD;
    int tid = threadIdx.x;

    float v0 = xr[tid], v1 = xr[tid + 256], v2 = xr[tid + 512];
    float sum = v0 + v1 + v2;
    float sq  = v0*v0 + v1*v1 + v2*v2;
    s1[tid] = sum; s2[tid] = sq;
    __syncthreads();
    for (int o = 128; o > 0; o >>= 1) {
        if (tid < o) { s1[tid] += s1[tid+o]; s2[tid] += s2[tid+o]; }
        __syncthreads();
    }
    float mean = s1[0] * (1.0f / DD);
    float var  = s2[0] * (1.0f / DD) - mean * mean;
    float inv  = rsqrtf(var + 1e-5f);
    yr[tid]       = tf32r((v0 - mean) * inv * g[tid]       + b[tid]);
    yr[tid + 256] = tf32r((v1 - mean) * inv * g[tid + 256] + b[tid + 256]);
    yr[tid + 512] = tf32r((v2 - mean) * inv * g[tid + 512] + b[tid + 512]);
}

// ---------------- prep: pack rel indices; round all weights to tf32 ----------------
__global__ void pack_kernel(const int* __restrict__ relm, unsigned char* __restrict__ out, int n)
{
    int i = blockIdx.x * 256 + threadIdx.x;
    if (i < n) out[i] = (unsigned char)(relm[i] + 1);
}

__global__ void round4_kernel(const float4* __restrict__ s0, int n0,
                              const float4* __restrict__ s1, int n1,
                              const float4* __restrict__ s2, int n2,
                              const float4* __restrict__ s3, int n3,
                              float4* __restrict__ dst)
{
    int i = blockIdx.x * 256 + threadIdx.x;
    const float4* s;
    int j = i;
    if (j < n0) s = s0;
    else { j -= n0;
        if (j < n1) { s = s1; }
        else { j -= n1;
            if (j < n2) { s = s2; }
            else { j -= n2; if (j >= n3) return; s = s3; }
        }
    }
    float4 v = s[j];
    v.x = tf32r(v.x); v.y = tf32r(v.y); v.z = tf32r(v.z); v.w = tf32r(v.w);
    dst[i] = v;
}

// ================= flash attention (pre-rounded tf32 operands) =================
#define AKSTR 76
#define PSTR 68
#define FKS_OFF 0
#define FVS_OFF (2 * 64 * AKSTR)
#define FPQ_OFF (FVS_OFF + 2 * 64 * AKSTR)
#define FRR_OFF (FPQ_OFF + 64 * PSTR)
#define FM_OFF  (FRR_OFF + 192)
#define FL_OFF  (FM_OFF + 64)
#define FSC_OFF (FL_OFF + 64)
#define FPM_OFF (FSC_OFF + 64)
#define FPS_OFF (FPM_OFF + 128)
#define FATTN_FLOATS (FPS_OFF + 128)
#define FATTN_SMEM (FATTN_FLOATS * 4)

__global__ void __launch_bounds__(256, 2) flash_attn_kernel(
    const float* __restrict__ qkv,
    const unsigned char* __restrict__ relpack,
    const unsigned char* __restrict__ mask,
    const float* __restrict__ relA,
    float* __restrict__ out)
{
    extern __shared__ float sm[];
    uint32_t sb32 = smem_to_u32(sm);
    float* Pq  = sm + FPQ_OFF;
    float* rr  = sm + FRR_OFF;
    float* m_s = sm + FM_OFF;
    float* l_s = sm + FL_OFF;
    float* sc_s= sm + FSC_OFF;
    float* pm  = sm + FPM_OFF;
    float* ps  = sm + FPS_OFF;

    int tid = threadIdx.x;
    int warp = tid >> 5, lane = tid & 31;
    int g = lane >> 2, t = lane & 3;
    int wq = warp & 3, wk = warp >> 2;
    int q0 = blockIdx.x * 64;
    int h  = blockIdx.y;
    int b  = blockIdx.z;
    const float* base = qkv + (size_t)b * SS * TD;
    const unsigned char* relrow = relpack + ((size_t)b * SS + q0) * SS;
    const unsigned char* maskp = mask + b * SS;

    // stage Q*0.125 (exact scale on tf32 data); init stats
    for (int i = tid; i < 64 * HD; i += 256) {
        int q = i >> 6, d = i & 63;
        Pq[q * PSTR + d] = base[(size_t)(q0 + q) * TD + h * HD + d] * 0.125f;
    }
    if (tid < 64) { m_s[tid] = -1e30f; l_s[tid] = 0.0f; }
    __syncthreads();

    // rel projections rr[q][c]  (scale folded via scaled Q)
    if (tid < 192) {
        int q = tid / 3, c = tid % 3;
        float s = 0.0f;
        #pragma unroll
        for (int d = 0; d < HD; d++) s += Pq[q * PSTR + d] * relA[c * HD + d];
        rr[q * 3 + c] = s;
    }

    // Q fragments (already tf32-valued bits)
    uint32_t qf[8][4];
    #pragma unroll
    for (int ks = 0; ks < 8; ks++) {
        const float* qp = Pq + (wq * 16 + g) * PSTR + ks * 8 + t;
        qf[ks][0] = F2U(qp[0]);
        qf[ks][1] = F2U(qp[8 * PSTR]);
        qf[ks][2] = F2U(qp[4]);
        qf[ks][3] = F2U(qp[8 * PSTR + 4]);
    }
    __syncthreads();

    auto load_tile = [&](int kt, int buf) {
        uint32_t sK = sb32 + (FKS_OFF + buf * 64 * AKSTR) * 4;
        uint32_t sV = sb32 + (FVS_OFF + buf * 64 * AKSTR) * 4;
        const float* srcK = base + (size_t)kt * 64 * TD + DD + h * HD;
        const float* srcV = base + (size_t)kt * 64 * TD + 2 * DD + h * HD;
        #pragma unroll
        for (int j = 0; j < 4; j++) {
            int e = tid + j * 256;
            int r = e >> 4, c = e & 15;
            uint32_t so = (uint32_t)(r * AKSTR + c * 4) * 4;
            cp16(sK + so, srcK + (size_t)r * TD + c * 4);
            cp16(sV + so, srcV + (size_t)r * TD + c * 4);
        }
        CP_COMMIT();
    };

    float oacc[4][4];
    #pragma unroll
    for (int nt = 0; nt < 4; nt++)
        #pragma unroll
        for (int e = 0; e < 4; e++) oacc[nt][e] = 0.0f;

    load_tile(0, 0);

    for (int kt = 0; kt < 16; kt++) {
        int buf = kt & 1;
        CP_WAIT(0);
        __syncthreads();                 // K/V ready; prior readers of buf^1 done
        if (kt + 1 < 16) load_tile(kt + 1, buf ^ 1);

        // prefetch rel idx + mask bytes
        unsigned idxv[4][4];
        unsigned mv[4][2];
        #pragma unroll
        for (int nt = 0; nt < 4; nt++) {
            #pragma unroll
            for (int e = 0; e < 4; e++) {
                int q  = wq * 16 + g + 8 * (e >> 1);
                int gk = kt * 64 + wk * 32 + nt * 8 + 2 * t + (e & 1);
                idxv[nt][e] = relrow[(size_t)q * SS + gk];
            }
            int gk0 = kt * 64 + wk * 32 + nt * 8 + 2 * t;
            mv[nt][0] = maskp[gk0];
            mv[nt][1] = maskp[gk0 + 1];
        }

        // S = Qs K^T
        float sacc[4][4];
        #pragma unroll
        for (int nt = 0; nt < 4; nt++)
            #pragma unroll
            for (int e = 0; e < 4; e++) sacc[nt][e] = 0.0f;
        const float* Kb = sm + FKS_OFF + buf * 64 * AKSTR;
        #pragma unroll
        for (int ks = 0; ks < 8; ks++) {
            uint32_t bf[4][2];
            #pragma unroll
            for (int nt = 0; nt < 4; nt++) {
                const float* kp = Kb + (wk * 32 + nt * 8 + g) * AKSTR + ks * 8 + t;
                bf[nt][0] = F2U(kp[0]);
                bf[nt][1] = F2U(kp[4]);
            }
            #pragma unroll
            for (int nt = 0; nt < 4; nt++)
                mma8(sacc[nt], qf[ks], bf[nt]);
        }

        // epilogue: +rel, mask; partial row max
        float rowmax[2] = {-1e30f, -1e30f};
        #pragma unroll
        for (int nt = 0; nt < 4; nt++) {
            #pragma unroll
            for (int e = 0; e < 4; e++) {
                int qr = wq * 16 + g + 8 * (e >> 1);
                float s = sacc[nt][e] + rr[qr * 3 + idxv[nt][e]];
                if (mv[nt][e & 1]) s = -1e30f;
                sacc[nt][e] = s;
                rowmax[e >> 1] = fmaxf(rowmax[e >> 1], s);
            }
        }
        #pragma unroll
        for (int o = 1; o <= 2; o <<= 1) {
            rowmax[0] = fmaxf(rowmax[0], __shfl_xor_sync(0xffffffffu, rowmax[0], o));
            rowmax[1] = fmaxf(rowmax[1], __shfl_xor_sync(0xffffffffu, rowmax[1], o));
        }
        if (t == 0) {
            pm[wk * 64 + wq * 16 + g]     = rowmax[0];
            pm[wk * 64 + wq * 16 + 8 + g] = rowmax[1];
        }
        __syncthreads();

        if (tid < 64) {
            float mo = m_s[tid];
            float mn = fmaxf(mo, fmaxf(pm[tid], pm[64 + tid]));
            m_s[tid] = mn;
            sc_s[tid] = __expf(mo - mn);
        }
        __syncthreads();

        // P = round(exp(s - m)); partial sums; rescale O
        float rowsum[2] = {0.0f, 0.0f};
        float mrow0 = m_s[wq * 16 + g], mrow1 = m_s[wq * 16 + 8 + g];
        #pragma unroll
        for (int nt = 0; nt < 4; nt++) {
            #pragma unroll
            for (int e = 0; e < 4; e++) {
                int qr = wq * 16 + g + 8 * (e >> 1);
                float p = tf32r(__expf(sacc[nt][e] - ((e >> 1) ? mrow1 : mrow0)));
                rowsum[e >> 1] += p;
                Pq[qr * PSTR + wk * 32 + nt * 8 + 2 * t + (e & 1)] = p;
            }
        }
        #pragma unroll
        for (int o = 1; o <= 2; o <<= 1) {
            rowsum[0] += __shfl_xor_sync(0xffffffffu, rowsum[0], o);
            rowsum[1] += __shfl_xor_sync(0xffffffffu, rowsum[1], o);
        }
        if (t == 0) {
            ps[wk * 64 + wq * 16 + g]     = rowsum[0];
            ps[wk * 64 + wq * 16 + 8 + g] = rowsum[1];
        }
        float s0 = sc_s[wq * 16 + g], s1 = sc_s[wq * 16 + 8 + g];
        #pragma unroll
        for (int nt = 0; nt < 4; nt++) {
            oacc[nt][0] *= s0; oacc[nt][1] *= s0;
            oacc[nt][2] *= s1; oacc[nt][3] *= s1;
        }
        __syncthreads();

        if (tid < 64)
            l_s[tid] = l_s[tid] * sc_s[tid] + ps[tid] + ps[64 + tid];

        // O += P @ V
        const float* Vb = sm + FVS_OFF + buf * 64 * AKSTR;
        #pragma unroll
        for (int ks = 0; ks < 8; ks++) {
            uint32_t af[4];
            const float* pp = Pq + (wq * 16 + g) * PSTR + ks * 8 + t;
            af[0] = F2U(pp[0]);
            af[1] = F2U(pp[8 * PSTR]);
            af[2] = F2U(pp[4]);
            af[3] = F2U(pp[8 * PSTR + 4]);
            uint32_t bf[4][2];
            #pragma unroll
            for (int nt = 0; nt < 4; nt++) {
                const float* vp = Vb + (ks * 8 + t) * AKSTR + wk * 32 + nt * 8 + g;
                bf[nt][0] = F2U(vp[0]);
                bf[nt][1] = F2U(vp[4 * AKSTR]);
            }
            #pragma unroll
            for (int nt = 0; nt < 4; nt++)
                mma8(oacc[nt], af, bf[nt]);
        }
    }
    __syncthreads();

    float inv0 = 1.0f / l_s[wq * 16 + g];
    float inv1 = 1.0f / l_s[wq * 16 + 8 + g];
    #pragma unroll
    for (int nt = 0; nt < 4; nt++) {
        #pragma unroll
        for (int e = 0; e < 4; e++) {
            int qr = wq * 16 + g + 8 * (e >> 1);
            int d  = wk * 32 + nt * 8 + 2 * t + (e & 1);
            out[((size_t)b * SS + q0 + qr) * DD + h * HD + d] =
                tf32r(oacc[nt][e] * ((e >> 1) ? inv1 : inv0));
        }
    }
}

// ---------------- launcher ----------------
extern "C" void kernel_launch(void* const* d_in, const int* in_sizes, int n_in,
                              void* d_out, int out_size)
{
    const float*         inp   = (const float*)d_in[0];
    const unsigned char* mask  = (const unsigned char*)d_in[1];
    const int*           relm  = (const int*)d_in[2];
    const float*         qkv_w = (const float*)d_in[3];
    const float*         relA  = (const float*)d_in[4];
    const float*         o_w   = (const float*)d_in[5];
    const float*         w1    = (const float*)d_in[6];
    const float*         b1    = (const float*)d_in[7];
    const float*         w2    = (const float*)d_in[8];
    const float*         b2    = (const float*)d_in[9];
    const float*         ln1g  = (const float*)d_in[10];
    const float*         ln1b  = (const float*)d_in[11];
    const float*         ln2g  = (const float*)d_in[12];
    const float*         ln2b  = (const float*)d_in[13];
    float* out = (float*)d_out;

    float *xln, *qkv, *attnout, *res1, *h1, *wr;
    unsigned char* relpack;
    cudaGetSymbolAddress((void**)&xln,     g_xln);
    cudaGetSymbolAddress((void**)&qkv,     g_qkv);
    cudaGetSymbolAddress((void**)&attnout, g_attnout);
    cudaGetSymbolAddress((void**)&res1,    g_res1);
    cudaGetSymbolAddress((void**)&h1,      g_h1);
    cudaGetSymbolAddress((void**)&wr,      g_wr);
    cudaGetSymbolAddress((void**)&relpack, g_relpack);

    cudaFuncSetAttribute(gemm_mma_kernel, cudaFuncAttributeMaxDynamicSharedMemorySize, GEMM_SMEM);
    cudaFuncSetAttribute(flash_attn_kernel, cudaFuncAttributeMaxDynamicSharedMemorySize, FATTN_SMEM);

    const float* qkv_wr = wr + W_QKV_OFF;
    const float* o_wr   = wr + W_O_OFF;
    const float* w1r    = wr + W_W1_OFF;
    const float* w2r    = wr + W_W2_OFF;

    // 0a) round all weights to tf32 into scratch (single fused kernel)
    {
        int n0 = TD * DD / 4, n1 = DD * DD / 4, n2 = DFF * DD / 4, n3 = DD * DFF / 4;
        int ntot = n0 + n1 + n2 + n3;
        round4_kernel<<<(ntot + 255) / 256, 256>>>(
            (const float4*)qkv_w, n0, (const float4*)o_w, n1,
            (const float4*)w1, n2, (const float4*)w2, n3, (float4*)wr);
    }
    // 0b) pack rel indices to u8
    pack_kernel<<<(BB * SS * SS + 255) / 256, 256>>>(relm, relpack, BB * SS * SS);

    // 1) LN1 (rounded output)
    ln_kernel<<<MROWS, 256>>>(inp, ln1g, ln1b, xln);

    // 2) QKV = xln @ qkv_w^T  (rounded output)
    gemm_mma_kernel<<<dim3(TD / 128, MROWS / 128), 256, GEMM_SMEM>>>(
        xln, qkv_wr, nullptr, nullptr, qkv, TD, DD, 0, 1);

    // 3) flash attention (rounded output)
    flash_attn_kernel<<<dim3(SS / 64, HH, BB), 256, FATTN_SMEM>>>(
        qkv, relpack, mask, relA, attnout);

    // 4) res1 = inp + attnout @ o_w^T  (fp32 output)
    gemm_mma_kernel<<<dim3(DD / 128, MROWS / 128), 256, GEMM_SMEM>>>(
        attnout, o_wr, nullptr, inp, res1, DD, DD, 0, 0);

    // 5) LN2 (rounded output)
    ln_kernel<<<MROWS, 256>>>(res1, ln2g, ln2b, xln);

    // 6) h1 = relu(xln @ w1^T + b1)  (rounded output)
    gemm_mma_kernel<<<dim3(DFF / 128, MROWS / 128), 256, GEMM_SMEM>>>(
        xln, w1r, b1, nullptr, h1, DFF, DD, 1, 1);

    // 7) out = res1 + h1 @ w2^T + b2  (fp32 output)
    gemm_mma_kernel<<<dim3(DD / 128, MROWS / 128), 256, GEMM_SMEM>>>(
        h1, w2r, b2, res1, out, DD, DFF, 0, 0);
}